// round 8
// baseline (speedup 1.0000x reference)
#include <cuda_runtime.h>
#include <cstddef>

// ChebychevTransform: x[8,256,256,8] f32 -> out[8,256,256,128] f32
// out[b,h,w, c*16 + p*4 + k] = sum_{i,j} T[p,j]*T[k,i]*x[b,h+i-1,w+j-1,c]
// (zero pad: 1 before / 2 after, TF SAME n=4)
// T = [[1/6,1/3,1/3,1/6],[1/3,1/3,-1/3,-1/3],[1/3,-1/3,-1/3,1/3],[1/3,-2/3,2/3,-1/3]]
//
// Warp = one (b, w, 8-row strip). lane = (j=lane>>3, c=lane&7).
// Stage 1 of the horizontal butterfly is done by DUAL LOADS (taps j and 3-j;
// both LDGs are the same dense 128B line set, lane-permuted) -> no shfl.
// Stage 2 uses one shfl_xor(8) per row. Vertical per-lane; dense STG.128:
// lane writes float4 at (c*16 + bitrev2(j)*4) of each pixel's 512B block.

#define HH 256
#define WW 256
#define CC 8
#define SS 8
#define NR (SS + 3)

__device__ __forceinline__ void cheb4(float x0, float x1, float x2, float x3,
                                      float& y0, float& y1, float& y2, float& y3) {
    const float K3 = 1.0f / 3.0f;
    const float K6 = 1.0f / 6.0f;
    float s0 = x0 + x3, s1 = x1 + x2;
    float d0 = x0 - x3, d1 = x1 - x2;
    y0 = fmaf(s1, K3, s0 * K6);
    y1 = (d0 + d1) * K3;
    y2 = (s0 - s1) * K3;
    y3 = fmaf(d1, -2.0f, d0) * K3;
}

__global__ __launch_bounds__(256)
void cheb_kernel(const float* __restrict__ x, float* __restrict__ out) {
    const unsigned FULL = 0xffffffffu;
    int tid  = blockIdx.x * 256 + threadIdx.x;
    int lane = tid & 31;
    int wid  = tid >> 5;                 // 65536 warps
    int w    = wid & (WW - 1);
    int hs   = (wid >> 8) & 31;          // 32 strips of 8 rows
    int b    = wid >> 13;
    int h0   = hs * SS;

    int j  = lane >> 3;                  // horizontal tap 0..3
    int cl = lane & 7;                   // channel 0..7

    // two taps per lane: j and 3-j (both dense across the warp)
    int wa = w - 1 + j;                  // tap j
    int wb = w + 2 - j;                  // tap 3-j
    bool va = (wa >= 0) && (wa < WW);
    bool vb = (wb >= 0) && (wb < WW);
    const float* pa = x + ((size_t)b * HH * WW + min(max(wa, 0), WW - 1)) * CC + cl;
    const float* pb = x + ((size_t)b * HH * WW + min(max(wb, 0), WW - 1)) * CC + cl;

    // ---- load + stage-1 combine: av[t] = (j<2) ? xa+xb : xa-xb ----
    float av[NR];
    #pragma unroll
    for (int t = 0; t < NR; t++) {
        size_t roff = (size_t)min(max(h0 - 1 + t, 0), HH - 1) * (WW * CC);
        float xa = va ? pa[roff] : 0.0f;
        float xb = vb ? pb[roff] : 0.0f;
        av[t] = (j < 2) ? (xa + xb) : (xa - xb);
    }

    // ---- stage 2: one shfl per row, then zero vertical padding rows ----
    const float K3 = 1.0f / 3.0f, K6 = 1.0f / 6.0f, K23 = 2.0f / 3.0f;
    float ca = (j == 0) ? K6 : -K3;
    float cb = (j == 3) ? K23 : ((j == 2) ? -K3 : K3);

    float u[NR];
    #pragma unroll
    for (int t = 0; t < NR; t++) {
        float bv = __shfl_xor_sync(FULL, av[t], 8);
        float uu = fmaf(ca, av[t], cb * bv);
        int r = h0 - 1 + t;
        u[t] = (r >= 0 && r < HH) ? uu : 0.0f;
    }

    // ---- vertical butterflies + dense stores ----
    int p = ((j & 1) << 1) | (j >> 1);           // bitrev2
    float* outp = out + ((size_t)(b * HH + h0) * WW + w) * (CC * 16)
                      + (cl * 16 + p * 4);
    #pragma unroll
    for (int s = 0; s < SS; s++) {
        float4 o;
        cheb4(u[s], u[s + 1], u[s + 2], u[s + 3], o.x, o.y, o.z, o.w);
        *(float4*)(outp + (size_t)s * (WW * CC * 16)) = o;
    }
}

extern "C" void kernel_launch(void* const* d_in, const int* in_sizes, int n_in,
                              void* d_out, int out_size) {
    const float* x = (const float*)d_in[0];
    float* out = (float*)d_out;
    cheb_kernel<<<8192, 256>>>(x, out);
}

// round 9
// speedup vs baseline: 1.0806x; 1.0806x over previous
#include <cuda_runtime.h>
#include <cstddef>

// ChebychevTransform: x[8,256,256,8] f32 -> out[8,256,256,128] f32
// out[b,h,w, c*16 + p*4 + k] = sum_{i,j} T[p,j]*T[k,i]*x[b,h+i-1,w+j-1,c]
// (zero pad: 1 before / 2 after, TF SAME n=4)
// T = [[1/6,1/3,1/3,1/6],[1/3,1/3,-1/3,-1/3],[1/3,-1/3,-1/3,1/3],[1/3,-2/3,2/3,-1/3]]
//
// Warp = one (b, w, 8-row strip). lane = (j=lane>>3, c=lane&7).
// Loads:  one coalesced 128B LDG per row; interior strips (hs=1..30) use a single
//         base pointer + immediate offsets (no clamp ALU, no padding selects).
// Horiz:  in-warp butterfly: shfl_xor 24 (j<->3-j), then shfl_xor 8.
// Vert:   per-lane over the 11-row register window; edge strips zero the
//         padding rows (hs==0: row -1; hs==31: rows 256 AND 257).
// Stores: lane writes float4 at (c*16 + bitrev2(j)*4) -> 4 dense STG.128/px.

#define HH 256
#define WW 256
#define CC 8
#define SS 8
#define NR (SS + 3)
#define ROWF (WW * CC)   // floats per image row

__device__ __forceinline__ void cheb4(float x0, float x1, float x2, float x3,
                                      float& y0, float& y1, float& y2, float& y3) {
    const float K3 = 1.0f / 3.0f;
    const float K6 = 1.0f / 6.0f;
    float s0 = x0 + x3, s1 = x1 + x2;
    float d0 = x0 - x3, d1 = x1 - x2;
    y0 = fmaf(s1, K3, s0 * K6);
    y1 = (d0 + d1) * K3;
    y2 = (s0 - s1) * K3;
    y3 = fmaf(d1, -2.0f, d0) * K3;
}

__global__ __launch_bounds__(256)
void cheb_kernel(const float* __restrict__ x, float* __restrict__ out) {
    const unsigned FULL = 0xffffffffu;
    int tid  = blockIdx.x * 256 + threadIdx.x;
    int lane = tid & 31;
    int wid  = tid >> 5;                 // 65536 warps
    int w    = wid & (WW - 1);
    int hs   = (wid >> 8) & 31;          // 32 strips of 8 rows
    int b    = wid >> 13;
    int h0   = hs * SS;

    int j  = lane >> 3;                  // horizontal tap 0..3
    int cl = lane & 7;                   // channel 0..7

    // lane's load column (clamped) + validity at w edges
    int wj  = w - 1 + j;
    bool wv = (wj >= 0) && (wj < WW);
    int cw  = min(max(wj, 0), WW - 1);
    const float* lbase = x + ((size_t)b * HH * WW + cw) * CC + cl;

    // ---- load phase: 11 coalesced 128B LDGs ----
    float raw[NR];
    if (hs != 0 && hs != 31) {
        // interior fast path: base + immediate offsets, no clamps/selects
        const float* rp = lbase + (size_t)(h0 - 1) * ROWF;
        #pragma unroll
        for (int t = 0; t < NR; t++)
            raw[t] = rp[t * ROWF];
    } else {
        #pragma unroll
        for (int t = 0; t < NR; t++) {
            int rc = min(max(h0 - 1 + t, 0), HH - 1);
            raw[t] = lbase[(size_t)rc * ROWF];
        }
    }
    if (!wv) {
        #pragma unroll
        for (int t = 0; t < NR; t++) raw[t] = 0.0f;
    }

    // ---- horizontal butterfly via shuffles ----
    const float K3 = 1.0f / 3.0f, K6 = 1.0f / 6.0f, K23 = 2.0f / 3.0f;
    float ca = (j == 0) ? K6 : -K3;
    float cb = (j == 3) ? K23 : ((j == 2) ? -K3 : K3);

    float u[NR];
    #pragma unroll
    for (int t = 0; t < NR; t++) {
        float s  = __shfl_xor_sync(FULL, raw[t], 24);
        float av = (j < 2) ? (raw[t] + s) : (raw[t] - s);
        float bv = __shfl_xor_sync(FULL, av, 8);
        u[t] = fmaf(ca, av, cb * bv);
    }
    // vertical zero-padding rows (only edge strips)
    if (hs == 0)  u[0] = 0.0f;                       // row -1
    if (hs == 31) { u[NR - 2] = 0.0f; u[NR - 1] = 0.0f; }  // rows 256, 257

    // ---- vertical butterflies + dense stores ----
    int p = ((j & 1) << 1) | (j >> 1);               // bitrev2
    float* outp = out + ((size_t)(b * HH + h0) * WW + w) * (CC * 16)
                      + (cl * 16 + p * 4);
    #pragma unroll
    for (int s = 0; s < SS; s++) {
        float4 o;
        cheb4(u[s], u[s + 1], u[s + 2], u[s + 3], o.x, o.y, o.z, o.w);
        *(float4*)(outp + (size_t)s * (ROWF * 16)) = o;
    }
}

extern "C" void kernel_launch(void* const* d_in, const int* in_sizes, int n_in,
                              void* d_out, int out_size) {
    const float* x = (const float*)d_in[0];
    float* out = (float*)d_out;
    cheb_kernel<<<8192, 256>>>(x, out);
}

// round 10
// speedup vs baseline: 1.1328x; 1.0484x over previous
#include <cuda_runtime.h>
#include <cstddef>

// ChebychevTransform: x[8,256,256,8] f32 -> out[8,256,256,128] f32
// out[b,h,w, c*16 + p*4 + k] = sum_{i,j} T[p,j]*T[k,i]*x[b,h+i-1,w+j-1,c]
// (zero pad: 1 before / 2 after, TF SAME n=4)
// T = [[1/6,1/3,1/3,1/6],[1/3,1/3,-1/3,-1/3],[1/3,-1/3,-1/3,1/3],[1/3,-2/3,2/3,-1/3]]
//
// Warp = one (b, w, 8-row strip). lane = (j=lane>>3, c=lane&7).
// Loads:  one coalesced 128B LDG per row; interior strips use base+immediate
//         offsets (no clamp ALU). Horiz: 2-stage shfl butterfly (xor24, xor8).
// Vert:   per-lane over the 11-row register window; edge strips zero padding
//         rows (hs==0: row -1; hs==31: rows 256 AND 257).
// Stores: lane writes float4 at (c*16 + bitrev2(j)*4) -> 4 dense STG.128/px,
//         issued with .cs (evict-first) so the write-once 256MB stream does
//         not thrash L2 and evict the 16x-reused input stencil lines.

#define HH 256
#define WW 256
#define CC 8
#define SS 8
#define NR (SS + 3)
#define ROWF (WW * CC)   // floats per image row

__device__ __forceinline__ void cheb4(float x0, float x1, float x2, float x3,
                                      float& y0, float& y1, float& y2, float& y3) {
    const float K3 = 1.0f / 3.0f;
    const float K6 = 1.0f / 6.0f;
    float s0 = x0 + x3, s1 = x1 + x2;
    float d0 = x0 - x3, d1 = x1 - x2;
    y0 = fmaf(s1, K3, s0 * K6);
    y1 = (d0 + d1) * K3;
    y2 = (s0 - s1) * K3;
    y3 = fmaf(d1, -2.0f, d0) * K3;
}

__global__ __launch_bounds__(256)
void cheb_kernel(const float* __restrict__ x, float* __restrict__ out) {
    const unsigned FULL = 0xffffffffu;
    int tid  = blockIdx.x * 256 + threadIdx.x;
    int lane = tid & 31;
    int wid  = tid >> 5;                 // 65536 warps
    int w    = wid & (WW - 1);
    int hs   = (wid >> 8) & 31;          // 32 strips of 8 rows
    int b    = wid >> 13;
    int h0   = hs * SS;

    int j  = lane >> 3;                  // horizontal tap 0..3
    int cl = lane & 7;                   // channel 0..7

    // lane's load column (clamped) + validity at w edges
    int wj  = w - 1 + j;
    bool wv = (wj >= 0) && (wj < WW);
    int cw  = min(max(wj, 0), WW - 1);
    const float* lbase = x + ((size_t)b * HH * WW + cw) * CC + cl;

    // ---- load phase: 11 coalesced 128B LDGs ----
    float raw[NR];
    if (hs != 0 && hs != 31) {
        const float* rp = lbase + (size_t)(h0 - 1) * ROWF;
        #pragma unroll
        for (int t = 0; t < NR; t++)
            raw[t] = rp[t * ROWF];
    } else {
        #pragma unroll
        for (int t = 0; t < NR; t++) {
            int rc = min(max(h0 - 1 + t, 0), HH - 1);
            raw[t] = lbase[(size_t)rc * ROWF];
        }
    }
    if (!wv) {
        #pragma unroll
        for (int t = 0; t < NR; t++) raw[t] = 0.0f;
    }

    // ---- horizontal butterfly via shuffles ----
    const float K3 = 1.0f / 3.0f, K6 = 1.0f / 6.0f, K23 = 2.0f / 3.0f;
    float ca = (j == 0) ? K6 : -K3;
    float cb = (j == 3) ? K23 : ((j == 2) ? -K3 : K3);

    float u[NR];
    #pragma unroll
    for (int t = 0; t < NR; t++) {
        float s  = __shfl_xor_sync(FULL, raw[t], 24);
        float av = (j < 2) ? (raw[t] + s) : (raw[t] - s);
        float bv = __shfl_xor_sync(FULL, av, 8);
        u[t] = fmaf(ca, av, cb * bv);
    }
    if (hs == 0)  u[0] = 0.0f;                              // row -1
    if (hs == 31) { u[NR - 2] = 0.0f; u[NR - 1] = 0.0f; }   // rows 256, 257

    // ---- vertical butterflies + dense streaming stores ----
    int p = ((j & 1) << 1) | (j >> 1);               // bitrev2
    float* outp = out + ((size_t)(b * HH + h0) * WW + w) * (CC * 16)
                      + (cl * 16 + p * 4);
    #pragma unroll
    for (int s = 0; s < SS; s++) {
        float4 o;
        cheb4(u[s], u[s + 1], u[s + 2], u[s + 3], o.x, o.y, o.z, o.w);
        __stcs((float4*)(outp + (size_t)s * (ROWF * 16)), o);
    }
}

extern "C" void kernel_launch(void* const* d_in, const int* in_sizes, int n_in,
                              void* d_out, int out_size) {
    const float* x = (const float*)d_in[0];
    float* out = (float*)d_out;
    cheb_kernel<<<8192, 256>>>(x, out);
}